// round 1
// baseline (speedup 1.0000x reference)
#include <cuda_runtime.h>
#include <math.h>

#define NIMG   2
#define NLVL   5
#define KPL    1000
#define NCAND  5000
#define NSORT  8192
#define NWORDS 79
#define TOT_ELEMS 2095104
#define BBOX_CLIP 4.135166556742356f

__constant__ int   c_HW[NLVL]     = {262144, 65536, 16384, 4096, 1024};
__constant__ int   c_LOGHW[NLVL]  = {18, 16, 14, 12, 10};
__constant__ int   c_LOGW[NLVL]   = {9, 8, 7, 6, 5};
__constant__ int   c_STRIDE[NLVL] = {4, 8, 16, 32, 64};
__constant__ float c_SIZE[NLVL]   = {32.f, 64.f, 128.f, 256.f, 512.f};

struct Ptrs { const float* obj[NLVL]; const float* box[NLVL]; };

// ------------------------- device scratch -------------------------
__device__ unsigned g_hist1[10][65536];
__device__ unsigned g_hist2[10][65536];
__device__ unsigned g_selH[10];
__device__ unsigned g_cntGT1[10];
__device__ unsigned g_Kstar[10];
__device__ unsigned g_G[10];
__device__ unsigned g_R[10];
__device__ unsigned g_candIdx[10][KPL];
__device__ unsigned g_candCnt[10];
__device__ unsigned g_tieIdx[10][4096];
__device__ unsigned g_tieCnt[10];
__device__ float4   g_boxo[NIMG][NCAND];   // offset (NMS) boxes
__device__ float4   g_boxc[NIMG][NCAND];   // clipped output boxes
__device__ float    g_scr [NIMG][NCAND];   // sigmoid score
__device__ ulonglong2 g_key[NIMG][NSORT];  // 128-bit sort keys
__device__ int      g_rlvl[NIMG][NCAND];   // level per sorted rank
__device__ float4   g_sboxo[NIMG][NCAND];
__device__ float4   g_sboxc[NIMG][NCAND];
__device__ float    g_sscr [NIMG][NCAND];
__device__ int      g_nvalid[NIMG];
__device__ unsigned long long g_mask[NIMG][NCAND][NWORDS];

// ------------------------- helpers -------------------------
__device__ __forceinline__ unsigned mono(float f) {
    unsigned u = __float_as_uint(f);
    return u ^ ((u & 0x80000000u) ? 0xFFFFFFFFu : 0x80000000u);
}

__device__ __forceinline__ void edec(int e, int& lvl, int& r) {
    if      (e < 1572864) { lvl = 0; r = e; }
    else if (e < 1966080) { lvl = 1; r = e - 1572864; }
    else if (e < 2064384) { lvl = 2; r = e - 1966080; }
    else if (e < 2088960) { lvl = 3; r = e - 2064384; }
    else                  { lvl = 4; r = e - 2088960; }
}

// ------------------------- kernels -------------------------
__global__ void k_zero() {
    int tid = blockIdx.x * blockDim.x + threadIdx.x;
    int stride = gridDim.x * blockDim.x;
    unsigned* h1 = &g_hist1[0][0];
    unsigned* h2 = &g_hist2[0][0];
    for (int i = tid; i < 10 * 65536; i += stride) { h1[i] = 0; h2[i] = 0; }
    if (tid < 10) { g_candCnt[tid] = 0; g_tieCnt[tid] = 0; }
}

__global__ void k_hist1(Ptrs P) {
    int e = blockIdx.x * 256 + threadIdx.x;
    if (e >= TOT_ELEMS) return;
    int lvl, r; edec(e, lvl, r);
    int HW3 = 3 * c_HW[lvl];
    int n = (r >= HW3) ? 1 : 0;
    unsigned key = mono(P.obj[lvl][r]);
    atomicAdd(&g_hist1[n * 5 + lvl][key >> 16], 1u);
}

__global__ void k_find1() {
    int seg = blockIdx.x;
    __shared__ unsigned csum[256];
    const unsigned* h = g_hist1[seg];
    unsigned s = 0;
    int b0 = threadIdx.x * 256;
    for (int b = b0; b < b0 + 256; b++) s += h[b];
    csum[threadIdx.x] = s;
    __syncthreads();
    if (threadIdx.x == 0) {
        unsigned acc = 0; int csel = 0;
        for (int c = 255; c >= 0; c--) {
            if (acc + csum[c] >= 1000u) { csel = c; break; }
            acc += csum[c];
        }
        unsigned acc2 = acc; int bsel = csel * 256;
        for (int b = csel * 256 + 255; b >= csel * 256; b--) {
            if (acc2 + h[b] >= 1000u) { bsel = b; break; }
            acc2 += h[b];
        }
        g_selH[seg] = (unsigned)bsel;
        g_cntGT1[seg] = acc2;
    }
}

__global__ void k_hist2(Ptrs P) {
    int e = blockIdx.x * 256 + threadIdx.x;
    if (e >= TOT_ELEMS) return;
    int lvl, r; edec(e, lvl, r);
    int HW3 = 3 * c_HW[lvl];
    int n = (r >= HW3) ? 1 : 0;
    int seg = n * 5 + lvl;
    unsigned key = mono(P.obj[lvl][r]);
    if ((key >> 16) == g_selH[seg])
        atomicAdd(&g_hist2[seg][key & 0xFFFFu], 1u);
}

__global__ void k_find2() {
    int seg = blockIdx.x;
    __shared__ unsigned csum[256];
    const unsigned* h = g_hist2[seg];
    unsigned s = 0;
    int b0 = threadIdx.x * 256;
    for (int b = b0; b < b0 + 256; b++) s += h[b];
    csum[threadIdx.x] = s;
    __syncthreads();
    if (threadIdx.x == 0) {
        unsigned acc = g_cntGT1[seg]; int csel = 0;
        for (int c = 255; c >= 0; c--) {
            if (acc + csum[c] >= 1000u) { csel = c; break; }
            acc += csum[c];
        }
        unsigned acc2 = acc; int bsel = csel * 256;
        for (int b = csel * 256 + 255; b >= csel * 256; b--) {
            if (acc2 + h[b] >= 1000u) { bsel = b; break; }
            acc2 += h[b];
        }
        g_Kstar[seg] = (g_selH[seg] << 16) | (unsigned)bsel;
        g_G[seg] = acc2;
        g_R[seg] = 1000u - acc2;
    }
}

__global__ void k_compact(Ptrs P) {
    int e = blockIdx.x * 256 + threadIdx.x;
    if (e >= TOT_ELEMS) return;
    int lvl, r; edec(e, lvl, r);
    int HW = c_HW[lvl];
    int HW3 = 3 * HW;
    int n = (r >= HW3) ? 1 : 0;
    int seg = n * 5 + lvl;
    unsigned key = mono(P.obj[lvl][r]);
    unsigned K = g_Kstar[seg];
    if (key < K) return;
    int rem = r - n * HW3;
    int a = rem >> c_LOGHW[lvl];
    int p = rem & (HW - 1);
    unsigned m = (unsigned)(p * 3 + a);   // flattened index (h*W+w)*A + a
    if (key > K) {
        unsigned pos = atomicAdd(&g_candCnt[seg], 1u);
        g_candIdx[seg][pos] = m;
    } else {
        unsigned t = atomicAdd(&g_tieCnt[seg], 1u);
        if (t < 4096u) g_tieIdx[seg][t] = m;
    }
}

__global__ void k_ties() {
    int seg = blockIdx.x;
    unsigned T = g_tieCnt[seg]; if (T > 4096u) T = 4096u;
    unsigned R = g_R[seg];
    unsigned G = g_G[seg];
    for (unsigned e = threadIdx.x; e < T; e += blockDim.x) {
        unsigned mi = g_tieIdx[seg][e];
        unsigned rank = 0;
        for (unsigned j = 0; j < T; j++) rank += (g_tieIdx[seg][j] < mi) ? 1u : 0u;
        if (rank < R) g_candIdx[seg][G + rank] = mi;
    }
}

__global__ void k_decode(Ptrs P) {
    int gt = blockIdx.x * blockDim.x + threadIdx.x;
    int img = gt >> 13;
    int slot = gt & (NSORT - 1);
    if (img >= NIMG) return;
    if (slot >= NCAND) {   // padding for bitonic sort
        g_key[img][slot] = make_ulonglong2(0ull, 0ull);
        return;
    }
    int lvl = slot / KPL;
    int j = slot - lvl * KPL;
    unsigned idx = g_candIdx[img * 5 + lvl][j];

    int a = (int)(idx % 3u);
    int p = (int)(idx / 3u);
    int lw = c_LOGW[lvl];
    int wc = p & ((1 << lw) - 1);
    int hc = p >> lw;

    float size = c_SIZE[lvl];
    float ar = (a == 0) ? 0.5f : ((a == 1) ? 1.0f : 2.0f);
    float hr = sqrtf(ar);
    float wr = 1.0f / hr;
    float bw = rintf(0.5f * (wr * size));   // round-half-even like jnp.round
    float bh = rintf(0.5f * (hr * size));
    float xs = (float)(wc * c_STRIDE[lvl]);
    float ys = (float)(hc * c_STRIDE[lvl]);
    float x1a = xs - bw, x2a = xs + bw;
    float y1a = ys - bh, y2a = ys + bh;
    float wa = x2a - x1a, ha = y2a - y1a;
    float cxa = x1a + 0.5f * wa, cya = y1a + 0.5f * ha;

    int HW = c_HW[lvl];
    const float* ob = P.obj[lvl];
    const float* bx = P.box[lvl];
    float raw = ob[(img * 3 + a) * HW + p];
    int bb = (img * 12 + a * 4) * HW + p;
    float dx = bx[bb];
    float dy = bx[bb + HW];
    float dw = fminf(bx[bb + 2 * HW], BBOX_CLIP);
    float dh = fminf(bx[bb + 3 * HW], BBOX_CLIP);

    float cx = __fadd_rn(__fmul_rn(dx, wa), cxa);
    float cy = __fadd_rn(__fmul_rn(dy, ha), cya);
    float w  = __fmul_rn(expf(dw), wa);
    float h  = __fmul_rn(expf(dh), ha);
    float x1 = __fsub_rn(cx, __fmul_rn(0.5f, w));
    float y1 = __fsub_rn(cy, __fmul_rn(0.5f, h));
    float x2 = __fadd_rn(cx, __fmul_rn(0.5f, w));
    float y2 = __fadd_rn(cy, __fmul_rn(0.5f, h));

    float x1c = fminf(fmaxf(x1, 0.0f), 2048.0f);
    float y1c = fminf(fmaxf(y1, 0.0f), 2048.0f);
    float x2c = fminf(fmaxf(x2, 0.0f), 2048.0f);
    float y2c = fminf(fmaxf(y2, 0.0f), 2048.0f);

    float sc = 1.0f / (1.0f + expf(-raw));
    bool keep = (__fsub_rn(x2c, x1c) >= 1e-3f) &&
                (__fsub_rn(y2c, y1c) >= 1e-3f) &&
                (sc > 0.0f);
    float ms = keep ? sc : -INFINITY;
    float off = (float)lvl * 4097.0f;

    g_boxc[img][slot] = make_float4(x1c, y1c, x2c, y2c);
    g_boxo[img][slot] = make_float4(__fadd_rn(x1c, off), __fadd_rn(y1c, off),
                                    __fadd_rn(x2c, off), __fadd_rn(y2c, off));
    g_scr[img][slot] = sc;

    unsigned mms = mono(ms);
    unsigned mraw = mono(raw);
    unsigned long long hi = ((unsigned long long)mms << 32) |
        (unsigned)(((unsigned)(7 - lvl) << 28) | (mraw >> 4));
    unsigned long long lo = ((unsigned long long)(mraw & 0xFu) << 60) |
        ((unsigned long long)((~idx) & 0xFFFFFu) << 40) |
        (unsigned long long)(unsigned)slot;
    g_key[img][slot] = make_ulonglong2(hi, lo);
}

// bitonic sort 8192 keys (descending), then gather sorted arrays
__global__ void k_sort() {
    extern __shared__ ulonglong2 sk[];
    int img = blockIdx.x;
    for (int i = threadIdx.x; i < NSORT; i += blockDim.x) sk[i] = g_key[img][i];
    __syncthreads();
    for (int k = 2; k <= NSORT; k <<= 1) {
        for (int j = k >> 1; j > 0; j >>= 1) {
            for (int i = threadIdx.x; i < NSORT; i += blockDim.x) {
                int l = i ^ j;
                if (l > i) {
                    ulonglong2 A = sk[i], B = sk[l];
                    bool lt = (A.x < B.x) || (A.x == B.x && A.y < B.y);
                    bool gt = (A.x > B.x) || (A.x == B.x && A.y > B.y);
                    bool up = (i & k) != 0;
                    if ((!up && lt) || (up && gt)) { sk[i] = B; sk[l] = A; }
                }
            }
            __syncthreads();
        }
    }
    for (int r = threadIdx.x; r < NCAND; r += blockDim.x) {
        ulonglong2 K = sk[r];
        int slot = (int)(K.y & 0xFFFFull);
        g_rlvl[img][r] = slot / KPL;
        g_sboxo[img][r] = g_boxo[img][slot];
        g_sboxc[img][r] = g_boxc[img][slot];
        g_sscr[img][r] = g_scr[img][slot];
        bool v = ((unsigned)(K.x >> 32)) >= 0x00800000u;   // ms > -inf
        bool vn = (r + 1 < NCAND) ? (((unsigned)(sk[r + 1].x >> 32)) >= 0x00800000u) : false;
        if (!v && r == 0) g_nvalid[img] = 0;
        if (v && !vn) g_nvalid[img] = r + 1;
    }
}

__device__ __forceinline__ float boxarea(float4 b) {
    return __fmul_rn(fmaxf(__fsub_rn(b.z, b.x), 0.0f),
                     fmaxf(__fsub_rn(b.w, b.y), 0.0f));
}

__global__ void k_mask() {
    int img = blockIdx.z, rb = blockIdx.y, cb = blockIdx.x;
    if (cb < rb) return;
    __shared__ float4 cbox[64];
    __shared__ int clvl[64];
    int t = threadIdx.x;
    int jg = cb * 64 + t;
    if (jg < NCAND) { cbox[t] = g_sboxo[img][jg]; clvl[t] = g_rlvl[img][jg]; }
    else clvl[t] = -1;
    __syncthreads();
    int i = rb * 64 + t;
    if (i >= NCAND) return;
    float4 bi = g_sboxo[img][i];
    int li = g_rlvl[img][i];
    float areai = boxarea(bi);
    unsigned long long bits = 0ull;
    int jj0 = (rb == cb) ? (t + 1) : 0;
    for (int jj = jj0; jj < 64; jj++) {
        if (clvl[jj] != li) continue;   // cross-level IoU is exactly 0
        float4 bj = cbox[jj];
        float ltx = fmaxf(bj.x, bi.x), lty = fmaxf(bj.y, bi.y);
        float rbx = fminf(bj.z, bi.z), rby = fminf(bj.w, bi.w);
        float wx = fmaxf(__fsub_rn(rbx, ltx), 0.0f);
        float wy = fmaxf(__fsub_rn(rby, lty), 0.0f);
        float inter = __fmul_rn(wx, wy);
        float areaj = boxarea(bj);
        float den = __fadd_rn(__fsub_rn(__fadd_rn(areaj, areai), inter), 1e-9f);
        float iou = __fdiv_rn(inter, den);
        if (iou > 0.7f) bits |= (1ull << jj);
    }
    g_mask[img][i][cb] = bits;
}

__global__ void k_scan(float* out) {
    int img = blockIdx.x;
    int lane = threadIdx.x;
    __shared__ unsigned long long supp[NWORDS];
    for (int c = lane; c < NWORDS; c += 32) supp[c] = 0ull;
    __syncwarp();
    int nv = g_nvalid[img];
    int kept = 0;
    for (int i = 0; i < nv && kept < KPL; i++) {
        unsigned long long wsup = supp[i >> 6];
        if (!((wsup >> (i & 63)) & 1ull)) {
            if (lane == 0) {
                float4 b = g_sboxc[img][i];
                float s = g_sscr[img][i];
                float* o = out + (img * KPL + kept) * 5;
                o[0] = b.x; o[1] = b.y; o[2] = b.z; o[3] = b.w; o[4] = s;
            }
            for (int c = (i >> 6) + lane; c < NWORDS; c += 32)
                supp[c] |= g_mask[img][i][c];
            kept++;
        }
        __syncwarp();
    }
    for (int r = kept + lane; r < KPL; r += 32) {
        float* o = out + (img * KPL + r) * 5;
        o[0] = 0.0f; o[1] = 0.0f; o[2] = 0.0f; o[3] = 0.0f; o[4] = 0.0f;
    }
}

// ------------------------- launch -------------------------
extern "C" void kernel_launch(void* const* d_in, const int* in_sizes, int n_in,
                              void* d_out, int out_size) {
    Ptrs P;
    // Identify input ordering by element counts.
    // obj sizes: {1572864,393216,98304,24576,6144}; box = 4x obj.
    if (in_sizes[0] == 6291456) {
        if (n_in > 2 && in_sizes[2] == 1572864 && in_sizes[1] == 1572864) {
            // interleaved box-first: box0, obj0, box1, obj1, ...
            for (int l = 0; l < NLVL; l++) { P.box[l] = (const float*)d_in[2 * l]; P.obj[l] = (const float*)d_in[2 * l + 1]; }
        } else {
            // grouped box-first: box0..box4, obj0..obj4
            for (int l = 0; l < NLVL; l++) { P.box[l] = (const float*)d_in[l]; P.obj[l] = (const float*)d_in[5 + l]; }
        }
    } else if (in_sizes[1] == 4 * in_sizes[0]) {
        // interleaved obj-first: obj0, box0, obj1, box1, ... (setup_inputs order)
        for (int l = 0; l < NLVL; l++) { P.obj[l] = (const float*)d_in[2 * l]; P.box[l] = (const float*)d_in[2 * l + 1]; }
    } else {
        // grouped obj-first: obj0..obj4, box0..box4
        for (int l = 0; l < NLVL; l++) { P.obj[l] = (const float*)d_in[l]; P.box[l] = (const float*)d_in[5 + l]; }
    }

    static bool attr_done = false;
    if (!attr_done) {
        cudaFuncSetAttribute(k_sort, cudaFuncAttributeMaxDynamicSharedMemorySize, NSORT * 16);
        attr_done = true;
    }

    const int NB = (TOT_ELEMS + 255) / 256;   // 8184
    k_zero<<<512, 256>>>();
    k_hist1<<<NB, 256>>>(P);
    k_find1<<<10, 256>>>();
    k_hist2<<<NB, 256>>>(P);
    k_find2<<<10, 256>>>();
    k_compact<<<NB, 256>>>(P);
    k_ties<<<10, 256>>>();
    k_decode<<<(NIMG * NSORT) / 256, 256>>>(P);
    k_sort<<<NIMG, 1024, NSORT * 16>>>();
    k_mask<<<dim3(NWORDS, NWORDS, NIMG), 64>>>();
    k_scan<<<NIMG, 32>>>((float*)d_out);
}

// round 2
// speedup vs baseline: 1.0749x; 1.0749x over previous
#include <cuda_runtime.h>
#include <math.h>

#define NIMG   2
#define NLVL   5
#define KPL    1000
#define NCAND  5000
#define NWORDS 79
#define TOT_ELEMS 2095104
#define BBOX_CLIP 4.135166556742356f

typedef unsigned long long ull;

__constant__ int   c_HW[NLVL]     = {262144, 65536, 16384, 4096, 1024};
__constant__ int   c_LOGHW[NLVL]  = {18, 16, 14, 12, 10};
__constant__ int   c_LOGW[NLVL]   = {9, 8, 7, 6, 5};
__constant__ int   c_STRIDE[NLVL] = {4, 8, 16, 32, 64};
__constant__ float c_SIZE[NLVL]   = {32.f, 64.f, 128.f, 256.f, 512.f};

struct Ptrs { const float* obj[NLVL]; const float* box[NLVL]; };

// ------------------------- device scratch -------------------------
__device__ unsigned g_hist1[10][65536];
__device__ unsigned g_hist2[10][65536];
__device__ unsigned g_selH[10];
__device__ unsigned g_cntGT1[10];
__device__ unsigned g_Kstar[10];
__device__ unsigned g_G[10];
__device__ unsigned g_R[10];
__device__ unsigned g_candIdx[10][KPL];
__device__ unsigned g_candCnt[10];
__device__ unsigned g_tieIdx[10][4096];
__device__ unsigned g_tieCnt[10];

__device__ float4   g_boxo[NIMG][NCAND];   // offset (NMS) boxes, by slot
__device__ float4   g_boxc[NIMG][NCAND];   // clipped output boxes, by slot
__device__ float    g_scr [NIMG][NCAND];   // sigmoid score, by slot
__device__ unsigned g_msr [NIMG][NCAND];   // mono(masked score), by slot
__device__ ull      g_lkey[NIMG][NLVL][1024];   // per-level sort keys
__device__ int      g_slotS[NIMG][NLVL][KPL];   // per-level sorted -> slot
__device__ unsigned g_msS  [NIMG][NLVL][KPL];   // per-level sorted ms (mono)

__device__ int      g_rlvl[NIMG][NCAND];   // level per global rank
__device__ float4   g_sboxo[NIMG][NCAND];
__device__ float4   g_sboxc[NIMG][NCAND];
__device__ float    g_sscr [NIMG][NCAND];
__device__ int      g_nvalid[NIMG];
__device__ ull      g_mask[NIMG][NCAND][NWORDS];

// ------------------------- helpers -------------------------
__device__ __forceinline__ unsigned mono(float f) {
    unsigned u = __float_as_uint(f);
    return u ^ ((u & 0x80000000u) ? 0xFFFFFFFFu : 0x80000000u);
}

__device__ __forceinline__ void edec(int e, int& lvl, int& r) {
    if      (e < 1572864) { lvl = 0; r = e; }
    else if (e < 1966080) { lvl = 1; r = e - 1572864; }
    else if (e < 2064384) { lvl = 2; r = e - 1966080; }
    else if (e < 2088960) { lvl = 3; r = e - 2064384; }
    else                  { lvl = 4; r = e - 2088960; }
}

// ------------------------- kernels -------------------------
__global__ void k_zero() {
    int tid = blockIdx.x * blockDim.x + threadIdx.x;
    int stride = gridDim.x * blockDim.x;
    unsigned* h1 = &g_hist1[0][0];
    unsigned* h2 = &g_hist2[0][0];
    for (int i = tid; i < 10 * 65536; i += stride) { h1[i] = 0; h2[i] = 0; }
    if (tid < 10) { g_candCnt[tid] = 0; g_tieCnt[tid] = 0; }
    if (tid < NIMG) g_nvalid[tid] = 0;
}

__global__ void k_hist1(Ptrs P) {
    int e = blockIdx.x * 256 + threadIdx.x;
    if (e >= TOT_ELEMS) return;
    int lvl, r; edec(e, lvl, r);
    int HW3 = 3 * c_HW[lvl];
    int n = (r >= HW3) ? 1 : 0;
    unsigned key = mono(P.obj[lvl][r]);
    atomicAdd(&g_hist1[n * 5 + lvl][key >> 16], 1u);
}

__global__ void k_find1() {
    int seg = blockIdx.x;
    __shared__ unsigned csum[256];
    const unsigned* h = g_hist1[seg];
    unsigned s = 0;
    int b0 = threadIdx.x * 256;
    for (int b = b0; b < b0 + 256; b++) s += h[b];
    csum[threadIdx.x] = s;
    __syncthreads();
    if (threadIdx.x == 0) {
        unsigned acc = 0; int csel = 0;
        for (int c = 255; c >= 0; c--) {
            if (acc + csum[c] >= 1000u) { csel = c; break; }
            acc += csum[c];
        }
        unsigned acc2 = acc; int bsel = csel * 256;
        for (int b = csel * 256 + 255; b >= csel * 256; b--) {
            if (acc2 + h[b] >= 1000u) { bsel = b; break; }
            acc2 += h[b];
        }
        g_selH[seg] = (unsigned)bsel;
        g_cntGT1[seg] = acc2;
    }
}

__global__ void k_hist2(Ptrs P) {
    int e = blockIdx.x * 256 + threadIdx.x;
    if (e >= TOT_ELEMS) return;
    int lvl, r; edec(e, lvl, r);
    int HW3 = 3 * c_HW[lvl];
    int n = (r >= HW3) ? 1 : 0;
    int seg = n * 5 + lvl;
    unsigned key = mono(P.obj[lvl][r]);
    if ((key >> 16) == g_selH[seg])
        atomicAdd(&g_hist2[seg][key & 0xFFFFu], 1u);
}

__global__ void k_find2() {
    int seg = blockIdx.x;
    __shared__ unsigned csum[256];
    const unsigned* h = g_hist2[seg];
    unsigned s = 0;
    int b0 = threadIdx.x * 256;
    for (int b = b0; b < b0 + 256; b++) s += h[b];
    csum[threadIdx.x] = s;
    __syncthreads();
    if (threadIdx.x == 0) {
        unsigned acc = g_cntGT1[seg]; int csel = 0;
        for (int c = 255; c >= 0; c--) {
            if (acc + csum[c] >= 1000u) { csel = c; break; }
            acc += csum[c];
        }
        unsigned acc2 = acc; int bsel = csel * 256;
        for (int b = csel * 256 + 255; b >= csel * 256; b--) {
            if (acc2 + h[b] >= 1000u) { bsel = b; break; }
            acc2 += h[b];
        }
        g_Kstar[seg] = (g_selH[seg] << 16) | (unsigned)bsel;
        g_G[seg] = acc2;
        g_R[seg] = 1000u - acc2;
    }
}

__global__ void k_compact(Ptrs P) {
    int e = blockIdx.x * 256 + threadIdx.x;
    if (e >= TOT_ELEMS) return;
    int lvl, r; edec(e, lvl, r);
    int HW = c_HW[lvl];
    int HW3 = 3 * HW;
    int n = (r >= HW3) ? 1 : 0;
    int seg = n * 5 + lvl;
    unsigned key = mono(P.obj[lvl][r]);
    unsigned K = g_Kstar[seg];
    if (key < K) return;
    int rem = r - n * HW3;
    int a = rem >> c_LOGHW[lvl];
    int p = rem & (HW - 1);
    unsigned m = (unsigned)(p * 3 + a);   // flattened index (h*W+w)*A + a
    if (key > K) {
        unsigned pos = atomicAdd(&g_candCnt[seg], 1u);
        g_candIdx[seg][pos] = m;
    } else {
        unsigned t = atomicAdd(&g_tieCnt[seg], 1u);
        if (t < 4096u) g_tieIdx[seg][t] = m;
    }
}

__global__ void k_ties() {
    int seg = blockIdx.x;
    unsigned T = g_tieCnt[seg]; if (T > 4096u) T = 4096u;
    unsigned R = g_R[seg];
    unsigned G = g_G[seg];
    for (unsigned e = threadIdx.x; e < T; e += blockDim.x) {
        unsigned mi = g_tieIdx[seg][e];
        unsigned rank = 0;
        for (unsigned j = 0; j < T; j++) rank += (g_tieIdx[seg][j] < mi) ? 1u : 0u;
        if (rank < R) g_candIdx[seg][G + rank] = mi;
    }
}

__global__ void k_decode(Ptrs P) {
    int gt = blockIdx.x * blockDim.x + threadIdx.x;   // 0 .. NIMG*5120-1
    int img = gt / 5120;
    if (img >= NIMG) return;
    int rem = gt - img * 5120;
    int lvl = rem >> 10;
    int j = rem & 1023;
    if (j >= KPL) { g_lkey[img][lvl][j] = 0ull; return; }
    unsigned idx = g_candIdx[img * 5 + lvl][j];

    int a = (int)(idx % 3u);
    int p = (int)(idx / 3u);
    int lw = c_LOGW[lvl];
    int wc = p & ((1 << lw) - 1);
    int hc = p >> lw;

    float size = c_SIZE[lvl];
    float ar = (a == 0) ? 0.5f : ((a == 1) ? 1.0f : 2.0f);
    float hr = sqrtf(ar);
    float wr = 1.0f / hr;
    float bw = rintf(0.5f * (wr * size));
    float bh = rintf(0.5f * (hr * size));
    float xs = (float)(wc * c_STRIDE[lvl]);
    float ys = (float)(hc * c_STRIDE[lvl]);
    float x1a = xs - bw, x2a = xs + bw;
    float y1a = ys - bh, y2a = ys + bh;
    float wa = x2a - x1a, ha = y2a - y1a;
    float cxa = x1a + 0.5f * wa, cya = y1a + 0.5f * ha;

    int HW = c_HW[lvl];
    const float* ob = P.obj[lvl];
    const float* bx = P.box[lvl];
    float raw = ob[(img * 3 + a) * HW + p];
    int bb = (img * 12 + a * 4) * HW + p;
    float dx = bx[bb];
    float dy = bx[bb + HW];
    float dw = fminf(bx[bb + 2 * HW], BBOX_CLIP);
    float dh = fminf(bx[bb + 3 * HW], BBOX_CLIP);

    float cx = __fadd_rn(__fmul_rn(dx, wa), cxa);
    float cy = __fadd_rn(__fmul_rn(dy, ha), cya);
    float w  = __fmul_rn(expf(dw), wa);
    float h  = __fmul_rn(expf(dh), ha);
    float x1 = __fsub_rn(cx, __fmul_rn(0.5f, w));
    float y1 = __fsub_rn(cy, __fmul_rn(0.5f, h));
    float x2 = __fadd_rn(cx, __fmul_rn(0.5f, w));
    float y2 = __fadd_rn(cy, __fmul_rn(0.5f, h));

    float x1c = fminf(fmaxf(x1, 0.0f), 2048.0f);
    float y1c = fminf(fmaxf(y1, 0.0f), 2048.0f);
    float x2c = fminf(fmaxf(x2, 0.0f), 2048.0f);
    float y2c = fminf(fmaxf(y2, 0.0f), 2048.0f);

    float sc = 1.0f / (1.0f + expf(-raw));
    bool keep = (__fsub_rn(x2c, x1c) >= 1e-3f) &&
                (__fsub_rn(y2c, y1c) >= 1e-3f) &&
                (sc > 0.0f);
    float ms = keep ? sc : -INFINITY;
    float off = (float)lvl * 4097.0f;

    int slot = lvl * KPL + j;
    g_boxc[img][slot] = make_float4(x1c, y1c, x2c, y2c);
    g_boxo[img][slot] = make_float4(__fadd_rn(x1c, off), __fadd_rn(y1c, off),
                                    __fadd_rn(x2c, off), __fadd_rn(y2c, off));
    g_scr[img][slot] = sc;
    g_msr[img][slot] = mono(ms);

    // per-level sort key: valid desc, raw desc, idx asc; j payload in low 10 bits
    ull key = ((ull)(keep ? 1u : 0u) << 62) |
              ((ull)mono(raw) << 30) |
              ((ull)((~idx) & 0xFFFFFu) << 10) |
              (ull)(unsigned)j;
    g_lkey[img][lvl][j] = key;
}

// per-(img,lvl) bitonic sort of 1024 64-bit keys, descending
__global__ void k_lsort() {
    __shared__ ull sk[1024];
    int img = blockIdx.x / NLVL;
    int lvl = blockIdx.x % NLVL;
    int tid = threadIdx.x;
    sk[tid] = g_lkey[img][lvl][tid];
    __syncthreads();
    for (int k = 2; k <= 1024; k <<= 1) {
        for (int j = k >> 1; j > 0; j >>= 1) {
            int l = tid ^ j;
            if (l > tid) {
                ull A = sk[tid], B = sk[l];
                bool up = (tid & k) != 0;
                if ((!up && A < B) || (up && A > B)) { sk[tid] = B; sk[l] = A; }
            }
            __syncthreads();
        }
    }
    bool v = false;
    if (tid < KPL) {
        ull k = sk[tid];
        int jj = (int)(k & 1023ull);
        int slot = lvl * KPL + jj;
        g_slotS[img][lvl][tid] = slot;
        g_msS[img][lvl][tid] = g_msr[img][slot];
        v = ((k >> 62) & 1ull) != 0ull;
    }
    unsigned bal = __ballot_sync(0xFFFFFFFFu, v);
    if ((tid & 31) == 0 && bal) atomicAdd((unsigned*)&g_nvalid[img], (unsigned)__popc(bal));
}

// merge-rank: global rank = own position + binary-search counts in other levels
__global__ void k_rank() {
    __shared__ unsigned sms[NLVL][KPL];
    int img = blockIdx.x;
    for (int i = threadIdx.x; i < NLVL * KPL; i += blockDim.x)
        sms[i / KPL][i % KPL] = g_msS[img][i / KPL][i % KPL];
    __syncthreads();
    for (int it = threadIdx.x; it < NLVL * KPL; it += blockDim.x) {
        int l = it / KPL, p = it % KPL;
        unsigned x = sms[l][p];
        int g = p;
        #pragma unroll
        for (int l2 = 0; l2 < NLVL; l2++) {
            if (l2 == l) continue;
            const unsigned* a = sms[l2];
            int lo = 0, hi = KPL;
            if (l2 < l) {  // count >= x
                while (lo < hi) { int mid = (lo + hi) >> 1; if (a[mid] >= x) lo = mid + 1; else hi = mid; }
            } else {       // count > x
                while (lo < hi) { int mid = (lo + hi) >> 1; if (a[mid] > x) lo = mid + 1; else hi = mid; }
            }
            g += lo;
        }
        int slot = g_slotS[img][l][p];
        g_rlvl[img][g] = l;
        g_sboxo[img][g] = g_boxo[img][slot];
        g_sboxc[img][g] = g_boxc[img][slot];
        g_sscr[img][g]  = g_scr[img][slot];
    }
}

__device__ __forceinline__ float boxarea(float4 b) {
    return __fmul_rn(fmaxf(__fsub_rn(b.z, b.x), 0.0f),
                     fmaxf(__fsub_rn(b.w, b.y), 0.0f));
}

__global__ void k_mask() {
    int img = blockIdx.z, rb = blockIdx.y, cb = blockIdx.x;
    if (cb < rb) return;
    int nv = g_nvalid[img];
    if (rb * 64 >= nv || cb * 64 >= nv) return;
    __shared__ float4 cbox[64];
    __shared__ int clvl[64];
    __shared__ unsigned hm[2][NLVL];
    __shared__ ull lmask[NLVL];
    int t = threadIdx.x;
    int jg = cb * 64 + t;
    int cl = -1;
    if (jg < NCAND) { cbox[t] = g_sboxo[img][jg]; cl = g_rlvl[img][jg]; }
    clvl[t] = cl;
    int w = t >> 5;
    #pragma unroll
    for (int l = 0; l < NLVL; l++) {
        unsigned b = __ballot_sync(0xFFFFFFFFu, cl == l);
        if ((t & 31) == 0) hm[w][l] = b;
    }
    __syncthreads();
    if (t < NLVL) lmask[t] = (ull)hm[0][t] | ((ull)hm[1][t] << 32);
    __syncthreads();
    int i = rb * 64 + t;
    if (i >= NCAND) return;
    float4 bi = g_sboxo[img][i];
    int li = g_rlvl[img][i];
    float areai = boxarea(bi);
    ull cand = lmask[li];
    if (rb == cb) cand &= (t == 63) ? 0ull : (~0ull << (t + 1));
    ull bits = 0ull;
    while (cand) {
        int jj = __ffsll((long long)cand) - 1;
        cand &= cand - 1ull;
        float4 bj = cbox[jj];
        float ltx = fmaxf(bj.x, bi.x), lty = fmaxf(bj.y, bi.y);
        float rbx = fminf(bj.z, bi.z), rby = fminf(bj.w, bi.w);
        float wx = fmaxf(__fsub_rn(rbx, ltx), 0.0f);
        float wy = fmaxf(__fsub_rn(rby, lty), 0.0f);
        float inter = __fmul_rn(wx, wy);
        float areaj = boxarea(bj);
        float den = __fadd_rn(__fsub_rn(__fadd_rn(areaj, areai), inter), 1e-9f);
        float iou = __fdiv_rn(inter, den);
        if (iou > 0.7f) bits |= 1ull << jj;
    }
    g_mask[img][i][cb] = bits;
}

// chunked greedy NMS scan: serial 64-bit register dance + parallel mask ORs
__global__ void k_scan(float* out) {
    int img = blockIdx.x;
    int ln = threadIdx.x;           // 32 threads
    __shared__ ull remv[NWORDS];
    for (int c = ln; c < NWORDS; c += 32) remv[c] = 0ull;
    __syncwarp();
    int nv = g_nvalid[img];
    int nch = (nv + 63) >> 6;
    int kept = 0;
    for (int c = 0; c < nch && kept < KPL; c++) {
        int base = c * 64;
        int r0 = base + ln, r1 = base + 32 + ln;
        ull m0 = (r0 < NCAND) ? g_mask[img][r0][c] : 0ull;
        ull m1 = (r1 < NCAND) ? g_mask[img][r1][c] : 0ull;
        ull w = remv[c];
        int lim = nv - base; if (lim > 64) lim = 64;
        ull keptbits = 0ull;
        int kc = 0;
        for (int b = 0; b < lim; b++) {
            if (!((w >> b) & 1ull)) {
                if (kept + kc >= KPL) break;
                keptbits |= 1ull << b;
                ull mr = __shfl_sync(0xFFFFFFFFu, (b < 32) ? m0 : m1, b & 31);
                w |= mr;
                kc++;
            }
        }
        // write kept outputs (lanes round-robin)
        {
            int cnt = 0;
            for (int b = 0; b < lim; b++) {
                if ((keptbits >> b) & 1ull) {
                    if ((cnt & 31) == ln) {
                        int i = base + b;
                        float4 bx = g_sboxc[img][i];
                        float s = g_sscr[img][i];
                        float* o = out + (img * KPL + kept + cnt) * 5;
                        o[0] = bx.x; o[1] = bx.y; o[2] = bx.z; o[3] = bx.w; o[4] = s;
                    }
                    cnt++;
                }
            }
        }
        kept += kc;
        // OR kept rows into future columns (lanes own distinct columns)
        for (int j = c + 1 + ln; j < nch; j += 32) {
            ull acc = remv[j];
            ull kb = keptbits;
            while (kb) {
                int b = __ffsll((long long)kb) - 1;
                kb &= kb - 1ull;
                acc |= g_mask[img][base + b][j];
            }
            remv[j] = acc;
        }
        __syncwarp();
    }
    for (int r = kept + ln; r < KPL; r += 32) {
        float* o = out + (img * KPL + r) * 5;
        o[0] = 0.0f; o[1] = 0.0f; o[2] = 0.0f; o[3] = 0.0f; o[4] = 0.0f;
    }
}

// ------------------------- launch -------------------------
extern "C" void kernel_launch(void* const* d_in, const int* in_sizes, int n_in,
                              void* d_out, int out_size) {
    Ptrs P;
    if (in_sizes[0] == 6291456) {
        if (n_in > 2 && in_sizes[2] == 1572864 && in_sizes[1] == 1572864) {
            for (int l = 0; l < NLVL; l++) { P.box[l] = (const float*)d_in[2 * l]; P.obj[l] = (const float*)d_in[2 * l + 1]; }
        } else {
            for (int l = 0; l < NLVL; l++) { P.box[l] = (const float*)d_in[l]; P.obj[l] = (const float*)d_in[5 + l]; }
        }
    } else if (in_sizes[1] == 4 * in_sizes[0]) {
        for (int l = 0; l < NLVL; l++) { P.obj[l] = (const float*)d_in[2 * l]; P.box[l] = (const float*)d_in[2 * l + 1]; }
    } else {
        for (int l = 0; l < NLVL; l++) { P.obj[l] = (const float*)d_in[l]; P.box[l] = (const float*)d_in[5 + l]; }
    }

    const int NB = (TOT_ELEMS + 255) / 256;   // 8184
    k_zero<<<512, 256>>>();
    k_hist1<<<NB, 256>>>(P);
    k_find1<<<10, 256>>>();
    k_hist2<<<NB, 256>>>(P);
    k_find2<<<10, 256>>>();
    k_compact<<<NB, 256>>>(P);
    k_ties<<<10, 256>>>();
    k_decode<<<(NIMG * 5120 + 255) / 256, 256>>>(P);
    k_lsort<<<NIMG * NLVL, 1024>>>();
    k_rank<<<NIMG, 1024>>>();
    k_mask<<<dim3(NWORDS, NWORDS, NIMG), 64>>>();
    k_scan<<<NIMG, 32>>>((float*)d_out);
}